// round 4
// baseline (speedup 1.0000x reference)
#include <cuda_runtime.h>
#include <cuda_bf16.h>
#include <cstddef>

// ---------------- problem constants ----------------
#define NA 200000      // atoms
#define NB 400000      // bonds
#define NM 10000       // molecules
#define AF 133         // atom feature dim
#define BF 13          // bond feature dim
#define HID 300        // hidden
#define NTASK 12
#define KI (AF + BF)   // 146
#define KO (AF + HID)  // 433
#define DEPTH 3

// ---------------- scratch (device globals; no allocation allowed) -------
static __device__ float g_h0[(size_t)NB * HID];    // 480 MB (persistent h0)
static __device__ float g_hA[(size_t)NB * HID];    // 480 MB (current h)
static __device__ float g_hB[(size_t)NB * HID];    // 480 MB (Y = h@W^T; later atom_h)
static __device__ float g_amsg[(size_t)NA * HID];  // 240 MB (per-atom sums)
static __device__ float g_molv[(size_t)NM * HID];  // 12 MB
static __device__ float g_out1[(size_t)NM * HID];  // 12 MB
static __device__ int   g_tgt[NB];                 // 1.6 MB (b2a[b2revb[b]])

// ---------------- register-tiled SGEMM: C = epi(Aeff @ W^T) -------------
// W is [N, K] row-major (torch Linear), C[r,c] = sum_k Aeff[r,k] * W[c,k].
// MODE 0: Aeff = A0 [M,K] dense
// MODE 1: Aeff[r,k] = (k<AF) ? A0[i0[r]*AF + k] : A1[r*BF + (k-AF)]   (h0 init)
// MODE 3: Aeff[r,k] = (k<AF) ? A0[r*AF + k]    : A1[r*HID + (k-AF)]  (readout)
constexpr int BM = 128, BN = 64, BK = 16, TM = 8, TN = 4;  // 256 threads

template <int MODE>
__global__ __launch_bounds__(256) void gemm_kernel(
    const float* __restrict__ A0, const float* __restrict__ A1,
    const int* __restrict__ i0,
    const float* __restrict__ W,
    const float* __restrict__ bias,
    float* __restrict__ C, int M, int N, int K, int do_relu)
{
    __shared__ float As[BK][BM + 4];   // row = 132 floats = 528 B (16B aligned)
    __shared__ float Bs[BK][BN + 4];   // row = 68 floats  = 272 B (16B aligned)
    __shared__ int   sI0[BM];

    const int tid  = threadIdx.x;
    const int row0 = blockIdx.y * BM;
    const int col0 = blockIdx.x * BN;

    if (MODE == 1) {
        if (tid < BM) {
            int r = row0 + tid;
            sI0[tid] = (r < M) ? i0[r] : 0;
        }
        __syncthreads();
    }

    float acc[TM][TN];
#pragma unroll
    for (int i = 0; i < TM; i++)
#pragma unroll
        for (int j = 0; j < TN; j++) acc[i][j] = 0.f;

    const int tr = tid / 16;   // 0..15 -> TM=8 rows each
    const int tc = tid % 16;   // 0..15 -> TN=4 cols each

    for (int k0 = 0; k0 < K; k0 += BK) {
        // --- A tile: BM x BK, 8 elems/thread, 16-wide coalesced along k ---
#pragma unroll
        for (int l = 0; l < (BM * BK) / 256; l++) {
            int lin = tid + l * 256;
            int k = lin & (BK - 1);
            int m = lin >> 4;
            int r = row0 + m;
            int kk = k0 + k;
            float v = 0.f;
            if (r < M && kk < K) {
                if (MODE == 0) {
                    v = A0[(size_t)r * K + kk];
                } else if (MODE == 1) {
                    v = (kk < AF) ? A0[(size_t)sI0[m] * AF + kk]
                                  : A1[(size_t)r * BF + (kk - AF)];
                } else { // MODE 3
                    v = (kk < AF) ? A0[(size_t)r * AF + kk]
                                  : A1[(size_t)r * HID + (kk - AF)];
                }
            }
            As[k][m] = v;
        }
        // --- W tile: Bs[k][n] = W[(col0+n)*K + k0+k], 4 elems/thread ---
#pragma unroll
        for (int l = 0; l < (BN * BK) / 256; l++) {
            int lin = tid + l * 256;
            int k = lin & (BK - 1);
            int n = lin >> 4;
            int c = col0 + n;
            int kk = k0 + k;
            Bs[k][n] = (c < N && kk < K) ? W[(size_t)c * K + kk] : 0.f;
        }
        __syncthreads();

#pragma unroll
        for (int k = 0; k < BK; k++) {
            float a[TM], b[TN];
            *reinterpret_cast<float4*>(&a[0]) =
                *reinterpret_cast<const float4*>(&As[k][tr * TM]);
            *reinterpret_cast<float4*>(&a[4]) =
                *reinterpret_cast<const float4*>(&As[k][tr * TM + 4]);
            *reinterpret_cast<float4*>(&b[0]) =
                *reinterpret_cast<const float4*>(&Bs[k][tc * TN]);
#pragma unroll
            for (int i = 0; i < TM; i++)
#pragma unroll
                for (int j = 0; j < TN; j++)
                    acc[i][j] = fmaf(a[i], b[j], acc[i][j]);
        }
        __syncthreads();
    }

#pragma unroll
    for (int i = 0; i < TM; i++) {
        int r = row0 + tr * TM + i;
        if (r >= M) continue;
#pragma unroll
        for (int j = 0; j < TN; j++) {
            int c = col0 + tc * TN + j;
            if (c >= N) continue;
            float v = acc[i][j];
            if (bias) v += bias[c];
            if (do_relu) v = fmaxf(v, 0.f);
            C[(size_t)r * N + c] = v;
        }
    }
}

// --------- target atoms: tgt[b] = b2a[b2revb[b]] ---------------------------
__global__ void tgt_kernel(const int* __restrict__ b2a,
                           const int* __restrict__ b2revb,
                           int* __restrict__ tgt)
{
    int b = blockIdx.x * blockDim.x + threadIdx.x;
    if (b < NB) tgt[b] = b2a[b2revb[b]];
}

// --------- scatter-add rows of X into acc by index idx[row] ----------------
__global__ void scatter_kernel(const float* __restrict__ X,
                               const int* __restrict__ idx,
                               float* __restrict__ acc, int nrows)
{
    const int CH = HID / 4; // 75 float4 per row
    int tid = blockIdx.x * blockDim.x + threadIdx.x;
    if (tid >= nrows * CH) return;
    int row = tid / CH;
    int c = tid % CH;
    int t = idx[row];
    float4 v = reinterpret_cast<const float4*>(X + (size_t)row * HID)[c];
    float* dst = acc + (size_t)t * HID + c * 4;
    atomicAdd(dst + 0, v.x);
    atomicAdd(dst + 1, v.y);
    atomicAdd(dst + 2, v.z);
    atomicAdd(dst + 3, v.w);
}

// --------- combine: h[b] = relu(h0[b] + amsg[b2a[b]] - Y[b2revb[b]]) -------
__global__ void combine_kernel(const float* __restrict__ h0,
                               const float* __restrict__ amsg,
                               const float* __restrict__ Y,
                               const int* __restrict__ b2a,
                               const int* __restrict__ b2revb,
                               float* __restrict__ hout)
{
    const int CH = HID / 4;
    int tid = blockIdx.x * blockDim.x + threadIdx.x;
    if (tid >= NB * CH) return;
    int bond = tid / CH;
    int c = tid % CH;
    int a  = b2a[bond];
    int rb = b2revb[bond];
    float4 v0 = reinterpret_cast<const float4*>(h0   + (size_t)bond * HID)[c];
    float4 va = reinterpret_cast<const float4*>(amsg + (size_t)a    * HID)[c];
    float4 vy = reinterpret_cast<const float4*>(Y    + (size_t)rb   * HID)[c];
    float4 r;
    r.x = fmaxf(v0.x + va.x - vy.x, 0.f);
    r.y = fmaxf(v0.y + va.y - vy.y, 0.f);
    r.z = fmaxf(v0.z + va.z - vy.z, 0.f);
    r.w = fmaxf(v0.w + va.w - vy.w, 0.f);
    reinterpret_cast<float4*>(hout + (size_t)bond * HID)[c] = r;
}

// --------- final logits: out[m,t] = out1[m,:] . W_r2[t,:] + b_r2[t] -------
__global__ void logits_kernel(const float* __restrict__ X,
                              const float* __restrict__ W2,
                              const float* __restrict__ b2,
                              float* __restrict__ out)
{
    int warp = (blockIdx.x * blockDim.x + threadIdx.x) >> 5;
    int lane = threadIdx.x & 31;
    if (warp >= NM) return;
    const float* x = X + (size_t)warp * HID;
    float acc[NTASK];
#pragma unroll
    for (int t = 0; t < NTASK; t++) acc[t] = 0.f;
    for (int k = lane; k < HID; k += 32) {
        float xv = x[k];
#pragma unroll
        for (int t = 0; t < NTASK; t++)
            acc[t] = fmaf(xv, W2[t * HID + k], acc[t]);
    }
#pragma unroll
    for (int t = 0; t < NTASK; t++) {
        float v = acc[t];
#pragma unroll
        for (int off = 16; off; off >>= 1)
            v += __shfl_down_sync(0xffffffffu, v, off);
        if (lane == 0) out[warp * NTASK + t] = v + b2[t];
    }
}

// ---------------- driver ----------------
extern "C" void kernel_launch(void* const* d_in, const int* in_sizes, int n_in,
                              void* d_out, int out_size)
{
    const float* f_atoms = (const float*)d_in[0];
    const float* f_bonds = (const float*)d_in[1];
    const int*   b2a     = (const int*)d_in[2];
    const int*   b2revb  = (const int*)d_in[3];
    const int*   mol_ids = (const int*)d_in[4];
    const float* W_i     = (const float*)d_in[5];
    const float* W_h     = (const float*)d_in[6];
    const float* W_o     = (const float*)d_in[7];
    const float* b_o     = (const float*)d_in[8];
    const float* W_r1    = (const float*)d_in[9];
    const float* b_r1    = (const float*)d_in[10];
    const float* W_r2    = (const float*)d_in[11];
    const float* b_r2    = (const float*)d_in[12];
    float* out = (float*)d_out;

    float *h0, *hA, *hB, *amsg, *molv, *out1;
    int* tgt;
    cudaGetSymbolAddress((void**)&h0,   g_h0);
    cudaGetSymbolAddress((void**)&hA,   g_hA);
    cudaGetSymbolAddress((void**)&hB,   g_hB);
    cudaGetSymbolAddress((void**)&amsg, g_amsg);
    cudaGetSymbolAddress((void**)&molv, g_molv);
    cudaGetSymbolAddress((void**)&out1, g_out1);
    cudaGetSymbolAddress((void**)&tgt,  g_tgt);

    const dim3 blk(256);
    const dim3 grid_hb((HID + BN - 1) / BN, (NB + BM - 1) / BM);  // 5 x 3125
    const dim3 grid_ha((HID + BN - 1) / BN, (NA + BM - 1) / BM);  // 5 x 1563
    const dim3 grid_hm((HID + BN - 1) / BN, (NM + BM - 1) / BM);  // 5 x 79

    // 0) target atom of each directed bond
    tgt_kernel<<<(NB + 255) / 256, blk>>>(b2a, b2revb, tgt);

    // 1) h0 = relu(concat(f_atoms[b2a], f_bonds) @ W_i^T)
    gemm_kernel<1><<<grid_hb, blk>>>(f_atoms, f_bonds, b2a,
                                     W_i, nullptr, h0, NB, HID, KI, 1);

    // 2) DEPTH message-passing rounds.
    //    Linear commutes with segment_sum:
    //      Y = h @ W_h^T (dense); atomY = scatter(Y, tgt);
    //      h' = relu(h0 + atomY[b2a] - Y[b2revb])
    const int scatB = ((NB * (HID / 4)) + 255) / 256;
    const int combB = scatB;
    float* h_cur = h0;
    for (int d = 0; d < DEPTH; d++) {
        gemm_kernel<0><<<grid_hb, blk>>>(h_cur, nullptr, nullptr,
                                         W_h, nullptr, hB, NB, HID, HID, 0);
        cudaMemsetAsync(amsg, 0, (size_t)NA * HID * sizeof(float));
        scatter_kernel<<<scatB, blk>>>(hB, tgt, amsg, NB);
        combine_kernel<<<combB, blk>>>(h0, amsg, hB, b2a, b2revb, hA);
        h_cur = hA;  // in-place across iterations (combine never reads hA)
    }

    // 3) final per-atom aggregation of h
    cudaMemsetAsync(amsg, 0, (size_t)NA * HID * sizeof(float));
    scatter_kernel<<<scatB, blk>>>(h_cur, tgt, amsg, NB);

    // 4) atom_h = relu(concat(f_atoms, amsg) @ W_o^T + b_o)  -> reuse hB
    gemm_kernel<3><<<grid_ha, blk>>>(f_atoms, amsg, nullptr,
                                     W_o, b_o, hB, NA, HID, KO, 1);

    // 5) per-molecule sum pooling
    cudaMemsetAsync(molv, 0, (size_t)NM * HID * sizeof(float));
    const int poolB = ((NA * (HID / 4)) + 255) / 256;
    scatter_kernel<<<poolB, blk>>>(hB, mol_ids, molv, NA);

    // 6) readout head
    gemm_kernel<0><<<grid_hm, blk>>>(molv, nullptr, nullptr,
                                     W_r1, b_r1, out1, NM, HID, HID, 1);
    logits_kernel<<<(NM * 32 + 255) / 256, blk>>>(out1, W_r2, b_r2, out);
}

// round 8
// speedup vs baseline: 2.1384x; 2.1384x over previous
#include <cuda_runtime.h>
#include <cstdint>
#include <cstddef>

// ---------------- problem constants ----------------
#define NA 200000      // atoms
#define NB 400000      // bonds
#define NM 10000       // molecules
#define AF 133         // atom feature dim
#define BFD 13         // bond feature dim
#define HID 300        // hidden
#define NPAD 320       // padded hidden (5 x 64 N-tiles)
#define NT 5           // N tiles of 64
#define NTASK 12
#define DEPTH 3
#define KP_I 160       // padded K for h0 init  (146 -> 160)
#define KP_H 320       // padded K for W_h      (300 -> 320)
#define KP_O 448       // padded K for W_o      (433 -> 448)

// ---------------- scratch (device globals; no allocation allowed) -------
static __device__ float g_h0 [(size_t)NB * NPAD];   // 512 MB
static __device__ float g_h  [(size_t)NB * NPAD];   // 512 MB
static __device__ float g_Y  [(size_t)NB * NPAD];   // 512 MB
static __device__ float g_am [(size_t)NA * NPAD];   // 256 MB
static __device__ float g_am2[(size_t)NA * NPAD];   // 256 MB
static __device__ float g_Ain[(size_t)NA * KP_O];   // 358 MB (packed A)
static __device__ float g_mol[(size_t)NM * NPAD];
static __device__ float g_o1 [(size_t)NM * NPAD];
static __device__ float g_WpI[(size_t)NPAD * KP_I];
static __device__ float g_WpH[(size_t)NPAD * KP_H];
static __device__ float g_WpO[(size_t)NPAD * KP_O];
static __device__ float g_WpR[(size_t)NPAD * KP_H];
static __device__ float g_bO [NPAD];
static __device__ float g_bR [NPAD];
static __device__ float g_zb [NPAD];                // stays zero
static __device__ int   g_tgt[NB];

__device__ __forceinline__ uint32_t f2tf32(float x) {
    uint32_t r; asm("cvt.rna.tf32.f32 %0, %1;" : "=r"(r) : "f"(x)); return r;
}
__device__ __forceinline__ void mma8(float* d, const uint32_t* a, const uint32_t* b) {
    asm volatile(
        "mma.sync.aligned.m16n8k8.row.col.f32.tf32.tf32.f32 "
        "{%0,%1,%2,%3}, {%4,%5,%6,%7}, {%8,%9}, {%0,%1,%2,%3};"
        : "+f"(d[0]), "+f"(d[1]), "+f"(d[2]), "+f"(d[3])
        : "r"(a[0]), "r"(a[1]), "r"(a[2]), "r"(a[3]), "r"(b[0]), "r"(b[1]));
}

// ================= tf32 mma.sync GEMM: C[M x 320] = epi(A[M x KP] @ Wp^T) ==
// Wp is [320 x KP] row-major. Grid = (NT, ceil(M/128)). CTA tile 128x64, BK=32.
// 8 warps: 4(M) x 2(N); warp tile 32x32 = 2 m-frags x 4 n-frags.
// SMEM layout: k within each 8-group permuted so (k, k+4) are adjacent ->
// every fragment load is a single LDS.64. Row stride 40 (4B banks: 4r+p mod 16
// distinct per half-warp phase -> conflict-free fragment loads).
// EPI 0: store Y (raw) + atomicAdd accb[ridx[r]*320 + c] for c<300
// EPI 1: relu(acc + biasp[c]); atomicAdd accb[ridx[r]*320 + c] for c<300
// EPI 2: relu(acc + biasp[c]); store Y
#define SA 40
template <int EPI>
__global__ __launch_bounds__(256, 2) void mma_gemm(
    const float* __restrict__ A, int M, int KP,
    const float* __restrict__ Wp, const float* __restrict__ biasp,
    const int* __restrict__ ridx,
    float* __restrict__ Y, float* __restrict__ accb)
{
    __shared__ __align__(16) uint32_t As[128 * SA];
    __shared__ __align__(16) uint32_t Ws[64 * SA];

    const int tid  = threadIdx.x;
    const int lane = tid & 31;
    const int wid  = tid >> 5;
    const int warpM = wid >> 1;        // 0..3
    const int warpN = wid & 1;         // 0..1
    const int row0 = blockIdx.y * 128;
    const int col0 = blockIdx.x * 64;
    const int nchunks = KP >> 5;

    // staging assignments
    const int arow = tid >> 1;          // 0..127
    const int akh  = (tid & 1) << 4;    // 0 or 16
    const int wrow = tid >> 2;          // 0..63
    const int wk8  = (tid & 3) << 3;    // 0,8,16,24
    const bool aval = (row0 + arow) < M;
    const float* aptr = A  + (size_t)(row0 + arow) * KP + akh;
    const float* wptr = Wp + (size_t)(col0 + wrow) * KP + wk8;

    float areg[16], wreg[8];
    // ---- prologue: load chunk 0 ----
    {
#pragma unroll
        for (int q = 0; q < 4; q++) {
            float4 v = aval ? *reinterpret_cast<const float4*>(aptr + q * 4)
                            : make_float4(0.f, 0.f, 0.f, 0.f);
            areg[q*4+0] = v.x; areg[q*4+1] = v.y; areg[q*4+2] = v.z; areg[q*4+3] = v.w;
        }
#pragma unroll
        for (int q = 0; q < 2; q++) {
            float4 v = *reinterpret_cast<const float4*>(wptr + q * 4);
            wreg[q*4+0] = v.x; wreg[q*4+1] = v.y; wreg[q*4+2] = v.z; wreg[q*4+3] = v.w;
        }
    }

    float acc[2][4][4];
#pragma unroll
    for (int i = 0; i < 2; i++)
#pragma unroll
        for (int j = 0; j < 4; j++)
#pragma unroll
            for (int q = 0; q < 4; q++) acc[i][j][q] = 0.f;

    for (int c = 0; c < nchunks; c++) {
        // ---- store stage (convert + paired-k permute) ----
#pragma unroll
        for (int g = 0; g < 2; g++) {
            uint32_t* base = &As[arow * SA + (akh >> 3) * 8 + g * 8];
#pragma unroll
            for (int w = 0; w < 4; w++) {
                uint2 p; p.x = f2tf32(areg[g*8+w]); p.y = f2tf32(areg[g*8+w+4]);
                *reinterpret_cast<uint2*>(base + 2 * w) = p;
            }
        }
        {
            uint32_t* base = &Ws[wrow * SA + (tid & 3) * 8];
#pragma unroll
            for (int w = 0; w < 4; w++) {
                uint2 p; p.x = f2tf32(wreg[w]); p.y = f2tf32(wreg[w+4]);
                *reinterpret_cast<uint2*>(base + 2 * w) = p;
            }
        }
        __syncthreads();
        // ---- prefetch next chunk into registers ----
        if (c + 1 < nchunks) {
            const float* ap = aptr + (size_t)(c + 1) * 32;
            const float* wp = wptr + (size_t)(c + 1) * 32;
#pragma unroll
            for (int q = 0; q < 4; q++) {
                float4 v = aval ? *reinterpret_cast<const float4*>(ap + q * 4)
                                : make_float4(0.f, 0.f, 0.f, 0.f);
                areg[q*4+0] = v.x; areg[q*4+1] = v.y; areg[q*4+2] = v.z; areg[q*4+3] = v.w;
            }
#pragma unroll
            for (int q = 0; q < 2; q++) {
                float4 v = *reinterpret_cast<const float4*>(wp + q * 4);
                wreg[q*4+0] = v.x; wreg[q*4+1] = v.y; wreg[q*4+2] = v.z; wreg[q*4+3] = v.w;
            }
        }
        // ---- mma over 4 k-steps ----
#pragma unroll
        for (int s = 0; s < 4; s++) {
            uint32_t a[2][4], b[4][2];
#pragma unroll
            for (int mf = 0; mf < 2; mf++) {
                int r = warpM * 32 + mf * 16 + (lane >> 2);
                uint2 lo = *reinterpret_cast<const uint2*>(
                    &As[r * SA + s * 8 + 2 * (lane & 3)]);
                uint2 hi = *reinterpret_cast<const uint2*>(
                    &As[(r + 8) * SA + s * 8 + 2 * (lane & 3)]);
                a[mf][0] = lo.x; a[mf][1] = hi.x; a[mf][2] = lo.y; a[mf][3] = hi.y;
            }
#pragma unroll
            for (int nf = 0; nf < 4; nf++) {
                int n = warpN * 32 + nf * 8 + (lane >> 2);
                uint2 bb = *reinterpret_cast<const uint2*>(
                    &Ws[n * SA + s * 8 + 2 * (lane & 3)]);
                b[nf][0] = bb.x; b[nf][1] = bb.y;
            }
#pragma unroll
            for (int mf = 0; mf < 2; mf++)
#pragma unroll
                for (int nf = 0; nf < 4; nf++)
                    mma8(acc[mf][nf], a[mf], b[nf]);
        }
        __syncthreads();
    }

    // ---- epilogue from register fragments ----
#pragma unroll
    for (int mf = 0; mf < 2; mf++) {
        int r0 = row0 + warpM * 32 + mf * 16 + (lane >> 2);
        int r1 = r0 + 8;
        bool v0 = r0 < M, v1 = r1 < M;
        int t0 = 0, t1 = 0;
        if (EPI == 0 || EPI == 1) {
            t0 = v0 ? ridx[r0] : 0;
            t1 = v1 ? ridx[r1] : 0;
        }
#pragma unroll
        for (int nf = 0; nf < 4; nf++) {
            int col = col0 + warpN * 32 + nf * 8 + 2 * (lane & 3);
            float c0 = acc[mf][nf][0], c1 = acc[mf][nf][1];
            float c2 = acc[mf][nf][2], c3 = acc[mf][nf][3];
            if (EPI == 1 || EPI == 2) {
                float2 bsv = *reinterpret_cast<const float2*>(&biasp[col]);
                c0 = fmaxf(c0 + bsv.x, 0.f); c1 = fmaxf(c1 + bsv.y, 0.f);
                c2 = fmaxf(c2 + bsv.x, 0.f); c3 = fmaxf(c3 + bsv.y, 0.f);
            }
            if (EPI == 0 || EPI == 2) {
                if (v0) *reinterpret_cast<float2*>(Y + (size_t)r0 * NPAD + col)
                            = make_float2(c0, c1);
                if (v1) *reinterpret_cast<float2*>(Y + (size_t)r1 * NPAD + col)
                            = make_float2(c2, c3);
            }
            if (EPI == 0 || EPI == 1) {
                if (col < HID) {
                    if (v0) {
                        float* p = accb + (size_t)t0 * NPAD + col;
                        atomicAdd(p, c0); atomicAdd(p + 1, c1);
                    }
                    if (v1) {
                        float* p = accb + (size_t)t1 * NPAD + col;
                        atomicAdd(p, c2); atomicAdd(p + 1, c3);
                    }
                }
            }
        }
    }
}

// --------- target atoms: tgt[b] = b2a[b2revb[b]] ---------------------------
__global__ void tgt_kernel(const int* __restrict__ b2a,
                           const int* __restrict__ b2revb,
                           int* __restrict__ tgt)
{
    int b = blockIdx.x * blockDim.x + threadIdx.x;
    if (b < NB) tgt[b] = b2a[b2revb[b]];
}

// --------- pack A for h0 init: [NB x 160] = concat(f_atoms[b2a], f_bonds, 0)
__global__ void pack_h0A(const float* __restrict__ fa, const float* __restrict__ fb,
                         const int* __restrict__ b2a, float* __restrict__ Ain)
{
    size_t idx = (size_t)blockIdx.x * blockDim.x + threadIdx.x;
    if (idx >= (size_t)NB * KP_I) return;
    int r = (int)(idx / KP_I), k = (int)(idx % KP_I);
    float v = 0.f;
    if (k < AF)            v = fa[(size_t)b2a[r] * AF + k];
    else if (k < AF + BFD) v = fb[(size_t)r * BFD + (k - AF)];
    Ain[idx] = v;
}

// --------- pack A for readout: [NA x 448] = concat(f_atoms, amsg, 0) -------
__global__ void pack_AoA(const float* __restrict__ fa, const float* __restrict__ am,
                         float* __restrict__ Ain)
{
    size_t idx = (size_t)blockIdx.x * blockDim.x + threadIdx.x;
    if (idx >= (size_t)NA * KP_O) return;
    int a = (int)(idx / KP_O), k = (int)(idx % KP_O);
    float v = 0.f;
    if (k < AF)            v = fa[(size_t)a * AF + k];
    else if (k < AF + HID) v = am[(size_t)a * NPAD + (k - AF)];
    Ain[idx] = v;
}

// --------- zero-pad a weight [rows x cols] into [320 x KP] ----------------
__global__ void pad_W(const float* __restrict__ src, int rows, int cols, int KP,
                      float* __restrict__ dst)
{
    int idx = blockIdx.x * blockDim.x + threadIdx.x;
    if (idx >= NPAD * KP) return;
    int rp = idx / KP, k = idx % KP;
    dst[idx] = (rp < rows && k < cols) ? src[(size_t)rp * cols + k] : 0.f;
}

__global__ void pad_bias(const float* __restrict__ src, float* __restrict__ dst)
{
    int c = threadIdx.x + blockIdx.x * blockDim.x;
    if (c < NPAD) dst[c] = (c < HID) ? src[c] : 0.f;
}

// --------- combine: h[b] = relu(h0[b] + amsg[b2a[b]] - Y[b2revb[b]]) -------
// FUSE: also atomicAdd h[b] into acc2[tgt[b]] (final bond->atom aggregation)
template <bool FUSE>
__global__ void combine_kernel(const float* __restrict__ h0,
                               const float* __restrict__ amsg,
                               const float* __restrict__ Y,
                               const int* __restrict__ b2a,
                               const int* __restrict__ b2revb,
                               float* __restrict__ hout,
                               const int* __restrict__ tgt,
                               float* __restrict__ acc2)
{
    const int CH = NPAD / 4; // 80
    size_t tid = (size_t)blockIdx.x * blockDim.x + threadIdx.x;
    if (tid >= (size_t)NB * CH) return;
    int bond = (int)(tid / CH);
    int c = (int)(tid % CH);
    int a  = b2a[bond];
    int rb = b2revb[bond];
    float4 v0 = reinterpret_cast<const float4*>(h0   + (size_t)bond * NPAD)[c];
    float4 va = reinterpret_cast<const float4*>(amsg + (size_t)a    * NPAD)[c];
    float4 vy = reinterpret_cast<const float4*>(Y    + (size_t)rb   * NPAD)[c];
    float4 r;
    r.x = fmaxf(v0.x + va.x - vy.x, 0.f);
    r.y = fmaxf(v0.y + va.y - vy.y, 0.f);
    r.z = fmaxf(v0.z + va.z - vy.z, 0.f);
    r.w = fmaxf(v0.w + va.w - vy.w, 0.f);
    reinterpret_cast<float4*>(hout + (size_t)bond * NPAD)[c] = r;
    if (FUSE) {
        if (c * 4 < HID) {  // pad cols are zero; skip their atomics
            float* dst = acc2 + (size_t)tgt[bond] * NPAD + c * 4;
            atomicAdd(dst + 0, r.x);
            atomicAdd(dst + 1, r.y);
            atomicAdd(dst + 2, r.z);
            atomicAdd(dst + 3, r.w);
        }
    }
}

// --------- final logits: out[m,t] = out1[m,:300] . W_r2[t,:] + b_r2[t] -----
__global__ void logits_kernel(const float* __restrict__ X,
                              const float* __restrict__ W2,
                              const float* __restrict__ b2,
                              float* __restrict__ out)
{
    int warp = (blockIdx.x * blockDim.x + threadIdx.x) >> 5;
    int lane = threadIdx.x & 31;
    if (warp >= NM) return;
    const float* x = X + (size_t)warp * NPAD;
    float acc[NTASK];
#pragma unroll
    for (int t = 0; t < NTASK; t++) acc[t] = 0.f;
    for (int k = lane; k < HID; k += 32) {
        float xv = x[k];
#pragma unroll
        for (int t = 0; t < NTASK; t++)
            acc[t] = fmaf(xv, W2[t * HID + k], acc[t]);
    }
#pragma unroll
    for (int t = 0; t < NTASK; t++) {
        float v = acc[t];
#pragma unroll
        for (int off = 16; off; off >>= 1)
            v += __shfl_down_sync(0xffffffffu, v, off);
        if (lane == 0) out[warp * NTASK + t] = v + b2[t];
    }
}

// ---------------- driver ----------------
extern "C" void kernel_launch(void* const* d_in, const int* in_sizes, int n_in,
                              void* d_out, int out_size)
{
    const float* f_atoms = (const float*)d_in[0];
    const float* f_bonds = (const float*)d_in[1];
    const int*   b2a     = (const int*)d_in[2];
    const int*   b2revb  = (const int*)d_in[3];
    const int*   mol_ids = (const int*)d_in[4];
    const float* W_i     = (const float*)d_in[5];
    const float* W_h     = (const float*)d_in[6];
    const float* W_o     = (const float*)d_in[7];
    const float* b_o     = (const float*)d_in[8];
    const float* W_r1    = (const float*)d_in[9];
    const float* b_r1    = (const float*)d_in[10];
    const float* W_r2    = (const float*)d_in[11];
    const float* b_r2    = (const float*)d_in[12];
    float* out = (float*)d_out;

    float *h0, *h, *Y, *am, *am2, *Ain, *mol, *o1;
    float *WpI, *WpH, *WpO, *WpR, *bO, *bR, *zb;
    int* tgt;
    cudaGetSymbolAddress((void**)&h0,  g_h0);
    cudaGetSymbolAddress((void**)&h,   g_h);
    cudaGetSymbolAddress((void**)&Y,   g_Y);
    cudaGetSymbolAddress((void**)&am,  g_am);
    cudaGetSymbolAddress((void**)&am2, g_am2);
    cudaGetSymbolAddress((void**)&Ain, g_Ain);
    cudaGetSymbolAddress((void**)&mol, g_mol);
    cudaGetSymbolAddress((void**)&o1,  g_o1);
    cudaGetSymbolAddress((void**)&WpI, g_WpI);
    cudaGetSymbolAddress((void**)&WpH, g_WpH);
    cudaGetSymbolAddress((void**)&WpO, g_WpO);
    cudaGetSymbolAddress((void**)&WpR, g_WpR);
    cudaGetSymbolAddress((void**)&bO,  g_bO);
    cudaGetSymbolAddress((void**)&bR,  g_bR);
    cudaGetSymbolAddress((void**)&zb,  g_zb);
    cudaGetSymbolAddress((void**)&tgt, g_tgt);

    const dim3 blk(256);

    // 0) indices + padded weights/biases
    tgt_kernel<<<(NB + 255) / 256, blk>>>(b2a, b2revb, tgt);
    pad_W<<<(NPAD * KP_I + 255) / 256, blk>>>(W_i,  HID, AF + BFD, KP_I, WpI);
    pad_W<<<(NPAD * KP_H + 255) / 256, blk>>>(W_h,  HID, HID,      KP_H, WpH);
    pad_W<<<(NPAD * KP_O + 255) / 256, blk>>>(W_o,  HID, AF + HID, KP_O, WpO);
    pad_W<<<(NPAD * KP_H + 255) / 256, blk>>>(W_r1, HID, HID,      KP_H, WpR);
    pad_bias<<<2, 256>>>(b_o,  bO);
    pad_bias<<<2, 256>>>(b_r1, bR);

    // 1) h0 = relu(concat(f_atoms[b2a], f_bonds) @ W_i^T)   [tf32 mma.sync]
    {
        size_t n = (size_t)NB * KP_I;
        pack_h0A<<<(unsigned)((n + 255) / 256), blk>>>(f_atoms, f_bonds, b2a, Ain);
        dim3 g(NT, NB / 128);
        mma_gemm<2><<<g, blk>>>(Ain, NB, KP_I, WpI, zb, nullptr, h0, nullptr);
    }

    // 2) DEPTH message rounds. Linear commutes with segment_sum:
    //    Y = h @ W_h^T (epilogue scatters Y into am by tgt);
    //    h' = relu(h0 + am[b2a] - Y[b2revb])  (round 3 also scatters h' -> am2)
    const unsigned combB = (unsigned)(((size_t)NB * (NPAD / 4) + 255) / 256);
    float* h_cur = h0;
    for (int d = 0; d < DEPTH; d++) {
        cudaMemsetAsync(am, 0, (size_t)NA * NPAD * sizeof(float));
        dim3 g(NT, NB / 128);
        mma_gemm<0><<<g, blk>>>(h_cur, NB, KP_H, WpH, nullptr, tgt, Y, am);
        if (d < DEPTH - 1) {
            combine_kernel<false><<<combB, blk>>>(h0, am, Y, b2a, b2revb, h,
                                                  nullptr, nullptr);
        } else {
            cudaMemsetAsync(am2, 0, (size_t)NA * NPAD * sizeof(float));
            combine_kernel<true><<<combB, blk>>>(h0, am, Y, b2a, b2revb, h,
                                                 tgt, am2);
        }
        h_cur = h;
    }

    // 3) atom readout fused with molecule pooling:
    //    mol += relu(concat(f_atoms, am2) @ W_o^T + b_o) scattered by mol_ids
    {
        size_t n = (size_t)NA * KP_O;
        pack_AoA<<<(unsigned)((n + 255) / 256), blk>>>(f_atoms, am2, Ain);
        cudaMemsetAsync(mol, 0, (size_t)NM * NPAD * sizeof(float));
        dim3 g(NT, (NA + 127) / 128);
        mma_gemm<1><<<g, blk>>>(Ain, NA, KP_O, WpO, bO, mol_ids, nullptr, mol);
    }

    // 4) readout head
    {
        dim3 g(NT, (NM + 127) / 128);
        mma_gemm<2><<<g, blk>>>(mol, NM, KP_H, WpR, bR, nullptr, o1, nullptr);
    }
    logits_kernel<<<(NM * 32 + 255) / 256, blk>>>(o1, W_r2, b_r2, out);
}